// round 4
// baseline (speedup 1.0000x reference)
#include <cuda_runtime.h>
#include <cuda_bf16.h>
#include <math.h>

// ---------------- problem constants ----------------
#define NNODES 50000
#define NEDGES 800000
#define NGRAPH 8
#define NPG    6250          // nodes per graph
#define CIN    512
#define HID    256
#define H3     768
#define KTOP   5000
#define CAP    96            // per-dst edge bucket capacity (deg ~ Poisson(16))

// ---------------- device scratch (static, no allocation) ----------------
__device__ __align__(256) float g_xw [NNODES * HID];   // GEMM output scratch
__device__ __align__(256) float g_x1 [NNODES * HID];
__device__ __align__(256) float g_x2 [NNODES * HID];
__device__ __align__(256) float g_x3 [NNODES * HID];
__device__ __align__(256) float g_deg[NNODES];         // sum of incoming ew, then dinv
__device__ __align__(256) int   g_cnt[NNODES];
__device__ __align__(256) int   g_eperm[NNODES * CAP]; // edge ids bucketed by dst
__device__ __align__(256) int   g_src [NEDGES];
__device__ __align__(256) float g_norm[NEDGES];
__device__ __align__(256) float g_score[NNODES];
__device__ __align__(256) float g_sel  [NNODES];       // score if selected else 0
__device__ unsigned g_thr[NGRAPH];
__device__ int      g_needeq[NGRAPH];
__device__ __align__(256) float g_readout[NGRAPH * 2 * H3];
__device__ float g_pwinv;

// device-side buffer selection (no host-side symbol address queries)
__device__ __forceinline__ float* buf_select(int sel) {
    switch (sel) {
        case 0:  return g_xw;
        case 1:  return g_x1;
        case 2:  return g_x2;
        default: return g_x3;
    }
}

// ---------------- setup kernels ----------------
__global__ void zero_kernel() {
    int i = blockIdx.x * 256 + threadIdx.x;
    if (i < NNODES) { g_deg[i] = 0.f; g_cnt[i] = 0; }
}

// edge_index is int32 (JAX default x64-disabled): row 0 = src, row 1 = dst
__global__ void fill_kernel(const int* __restrict__ ei,
                            const float* __restrict__ ea) {
    int e = blockIdx.x * 256 + threadIdx.x;
    if (e >= NEDGES) return;
    int s = ei[e];
    int d = ei[NEDGES + e];
    if ((unsigned)s >= NNODES || (unsigned)d >= NNODES) {
        g_src[e] = 0;   // defensive: never index OOB
        return;
    }
    g_src[e] = s;
    atomicAdd(&g_deg[d], ea[e]);
    int slot = atomicAdd(&g_cnt[d], 1);
    if (slot < CAP) g_eperm[d * CAP + slot] = e;
}

__global__ void dinv_kernel() {
    int i = blockIdx.x * 256 + threadIdx.x;
    if (i < NNODES) g_deg[i] = rsqrtf(g_deg[i] + 1.0f);
}

__global__ void norm_kernel(const int* __restrict__ ei,
                            const float* __restrict__ ea) {
    int e = blockIdx.x * 256 + threadIdx.x;
    if (e >= NEDGES) return;
    int d = ei[NEDGES + e];
    if ((unsigned)d >= NNODES) { g_norm[e] = 0.f; return; }
    int s = g_src[e];
    g_norm[e] = g_deg[s] * ea[e] * g_deg[d];
}

// ---------------- SGEMM: g_xw[M,256] = A[M,K] @ B[K,256] ----------------
// A: a_sel==0 -> external x, else g_x1/g_x2. 128x128x8 tiles, 256 threads.
__global__ __launch_bounds__(256) void sgemm_kernel(
    const float* __restrict__ x_ext, int a_sel,
    const float* __restrict__ B, int K)
{
    const float* A = (a_sel == 0) ? x_ext : (const float*)buf_select(a_sel);
    float* C = g_xw;

    __shared__ float As[8][128];
    __shared__ float Bs[8][128];
    const int tid = threadIdx.x;
    const int bm = blockIdx.y * 128;
    const int bn = blockIdx.x * 128;

    const int arow = tid >> 1;          // 0..127
    const int acol = (tid & 1) << 2;    // 0 or 4
    const int brow = tid >> 5;          // 0..7
    const int bcol = (tid & 31) << 2;   // 0..124
    const int tx = tid & 15, ty = tid >> 4;

    float acc[8][8];
#pragma unroll
    for (int i = 0; i < 8; i++)
#pragma unroll
        for (int j = 0; j < 8; j++) acc[i][j] = 0.f;

    const bool arow_ok = (bm + arow) < NNODES;
    const float* Aptr = A + (size_t)(bm + arow) * K + acol;

    for (int k0 = 0; k0 < K; k0 += 8) {
        float4 av = make_float4(0.f, 0.f, 0.f, 0.f);
        if (arow_ok) av = *(const float4*)(Aptr + k0);
        As[acol + 0][arow] = av.x;
        As[acol + 1][arow] = av.y;
        As[acol + 2][arow] = av.z;
        As[acol + 3][arow] = av.w;
        float4 bv = *(const float4*)(B + (size_t)(k0 + brow) * HID + bn + bcol);
        *(float4*)&Bs[brow][bcol] = bv;
        __syncthreads();
#pragma unroll
        for (int kk = 0; kk < 8; kk++) {
            float ra[8], rb[8];
#pragma unroll
            for (int i = 0; i < 8; i++) ra[i] = As[kk][ty * 8 + i];
#pragma unroll
            for (int j = 0; j < 8; j++) rb[j] = Bs[kk][tx * 8 + j];
#pragma unroll
            for (int i = 0; i < 8; i++)
#pragma unroll
                for (int j = 0; j < 8; j++)
                    acc[i][j] += ra[i] * rb[j];
        }
        __syncthreads();
    }

#pragma unroll
    for (int i = 0; i < 8; i++) {
        int row = bm + ty * 8 + i;
        if (row < NNODES) {
            float4 v0 = make_float4(acc[i][0], acc[i][1], acc[i][2], acc[i][3]);
            float4 v1 = make_float4(acc[i][4], acc[i][5], acc[i][6], acc[i][7]);
            *(float4*)&C[(size_t)row * HID + bn + tx * 8]     = v0;
            *(float4*)&C[(size_t)row * HID + bn + tx * 8 + 4] = v1;
        }
    }
}

// ---------------- GCN aggregation (gather, deterministic) ----------------
// out[i][f] = relu( sum_e norm[e]*xw[src[e]][f] + dinv[i]^2*xw[i][f] + b[f] )
__global__ __launch_bounds__(256) void agg_kernel(
    const float* __restrict__ bias, int out_sel)
{
    const float* xw = g_xw;
    float* out = buf_select(out_sel);
    const int node = blockIdx.x;
    const int t = threadIdx.x;
    __shared__ int   s_src[CAP];
    __shared__ float s_nrm[CAP];
    __shared__ int   s_cnt;
    if (t == 0) { int c = g_cnt[node]; s_cnt = c < CAP ? c : CAP; }
    __syncthreads();
    const int cnt = s_cnt;
    if (t < cnt) {
        int e = g_eperm[node * CAP + t];
        s_src[t] = g_src[e];
        s_nrm[t] = g_norm[e];
    }
    __syncthreads();

    float d = g_deg[node];
    float acc = d * d * xw[(size_t)node * HID + t] + bias[t];
    int j = 0;
    for (; j + 4 <= cnt; j += 4) {
        float v0 = xw[(size_t)s_src[j + 0] * HID + t];
        float v1 = xw[(size_t)s_src[j + 1] * HID + t];
        float v2 = xw[(size_t)s_src[j + 2] * HID + t];
        float v3 = xw[(size_t)s_src[j + 3] * HID + t];
        acc += s_nrm[j + 0] * v0;
        acc += s_nrm[j + 1] * v1;
        acc += s_nrm[j + 2] * v2;
        acc += s_nrm[j + 3] * v3;
    }
    for (; j < cnt; j++)
        acc += s_nrm[j] * xw[(size_t)s_src[j] * HID + t];
    out[(size_t)node * HID + t] = fmaxf(acc, 0.f);
}

// ---------------- scoring ----------------
__global__ void pwnorm_kernel(const float* __restrict__ pw) {
    __shared__ float red[256];
    float s = 0.f;
    for (int i = threadIdx.x; i < H3; i += 256) s += pw[i] * pw[i];
    red[threadIdx.x] = s;
    __syncthreads();
    for (int o = 128; o > 0; o >>= 1) {
        if (threadIdx.x < o) red[threadIdx.x] += red[threadIdx.x + o];
        __syncthreads();
    }
    if (threadIdx.x == 0) g_pwinv = rsqrtf(red[0]);
}

__global__ void score_kernel(const float* __restrict__ pw) {
    int node = blockIdx.x * 8 + (threadIdx.x >> 5);
    int lane = threadIdx.x & 31;
    float s = 0.f;
    size_t base = (size_t)node * HID;
#pragma unroll
    for (int f = 0; f < HID; f += 32) {
        int ff = f + lane;
        s += g_x1[base + ff] * pw[ff];
        s += g_x2[base + ff] * pw[HID + ff];
        s += g_x3[base + ff] * pw[2 * HID + ff];
    }
#pragma unroll
    for (int o = 16; o > 0; o >>= 1) s += __shfl_xor_sync(0xffffffffu, s, o);
    if (lane == 0) g_score[node] = 1.f / (1.f + expf(-s * g_pwinv));
}

// ---------------- exact top-K threshold per graph (radix select) -------
__global__ void radix_kernel() {
    const int g = blockIdx.x;
    const float* sc = g_score + g * NPG;
    __shared__ int hist[256];
    __shared__ unsigned s_prefix;
    __shared__ int s_remaining;
    if (threadIdx.x == 0) { s_prefix = 0u; s_remaining = KTOP; }
    __syncthreads();
    for (int pass = 3; pass >= 0; --pass) {
        hist[threadIdx.x] = 0;
        __syncthreads();
        unsigned prefix = s_prefix;
        int shift = pass * 8;
        for (int i = threadIdx.x; i < NPG; i += 256) {
            unsigned bits = __float_as_uint(sc[i]);   // positives: uint order = float order
            bool match = (pass == 3) || ((bits >> (shift + 8)) == prefix);
            if (match) atomicAdd(&hist[(bits >> shift) & 255u], 1);
        }
        __syncthreads();
        if (threadIdx.x == 0) {
            int rem = s_remaining;
            unsigned p = s_prefix;
            for (int b = 255; b >= 0; --b) {
                if (hist[b] >= rem) { s_prefix = (p << 8) | (unsigned)b; break; }
                rem -= hist[b];
            }
            s_remaining = rem;
        }
        __syncthreads();
    }
    if (threadIdx.x == 0) { g_thr[g] = s_prefix; g_needeq[g] = s_remaining; }
}

// stable tie resolution (lowest index first, matching lax.top_k)
__global__ void selscale_kernel() {
    const int g = blockIdx.x;
    const unsigned thr = g_thr[g];
    const int need = g_needeq[g];
    __shared__ int scan[256];
    __shared__ int s_carry;
    if (threadIdx.x == 0) s_carry = 0;
    __syncthreads();
    for (int base = 0; base < NPG; base += 256) {
        int i = base + threadIdx.x;
        float s = 0.f; unsigned bits = 0u;
        if (i < NPG) { s = g_score[g * NPG + i]; bits = __float_as_uint(s); }
        int eq = (i < NPG && bits == thr) ? 1 : 0;
        int carry = s_carry;
        __syncthreads();
        scan[threadIdx.x] = eq;
        __syncthreads();
        for (int o = 1; o < 256; o <<= 1) {
            int v = (threadIdx.x >= o) ? scan[threadIdx.x - o] : 0;
            __syncthreads();
            scan[threadIdx.x] += v;
            __syncthreads();
        }
        int excl = scan[threadIdx.x] - eq + carry;
        if (i < NPG) {
            float out = 0.f;
            if (bits > thr) out = s;
            else if (eq && excl < need) out = s;
            g_sel[g * NPG + i] = out;
        }
        int total = scan[255];
        __syncthreads();
        if (threadIdx.x == 0) s_carry = carry + total;
        __syncthreads();
    }
}

// ---------------- readout: mean & max of score-scaled selected rows ----
__global__ __launch_bounds__(256) void readout_kernel() {
    const int g = blockIdx.x / 3, c = blockIdx.x % 3;
    const float* X = (c == 0) ? g_x1 : ((c == 1) ? g_x2 : g_x3);
    const int f = threadIdx.x;
    const float* sel = g_sel + g * NPG;
    const size_t rowbase = (size_t)g * NPG * HID;
    float sum0 = 0.f, sum1 = 0.f, sum2 = 0.f, sum3 = 0.f;
    float mx = 0.f;   // selected entries are >= 0 (relu * positive score)
    int i = 0;
    for (; i + 4 <= NPG; i += 4) {
        float s0 = sel[i + 0], s1 = sel[i + 1], s2 = sel[i + 2], s3 = sel[i + 3];
        float v0 = s0 * X[rowbase + (size_t)(i + 0) * HID + f];
        float v1 = s1 * X[rowbase + (size_t)(i + 1) * HID + f];
        float v2 = s2 * X[rowbase + (size_t)(i + 2) * HID + f];
        float v3 = s3 * X[rowbase + (size_t)(i + 3) * HID + f];
        sum0 += v0; sum1 += v1; sum2 += v2; sum3 += v3;
        mx = fmaxf(mx, fmaxf(fmaxf(v0, v1), fmaxf(v2, v3)));
    }
    for (; i < NPG; i++) {
        float v = sel[i] * X[rowbase + (size_t)i * HID + f];
        sum0 += v; mx = fmaxf(mx, v);
    }
    float sum = (sum0 + sum1) + (sum2 + sum3);
    g_readout[g * 2 * H3 + c * HID + f]      = sum * (1.f / (float)KTOP);
    g_readout[g * 2 * H3 + H3 + c * HID + f] = mx;
}

// ---------------- final MLP: [8,1536] -> 256 -> 128 -> 3 ----------------
__global__ __launch_bounds__(256) void mlp_kernel(
    const float* __restrict__ lw1, const float* __restrict__ lb1,
    const float* __restrict__ lw2, const float* __restrict__ lb2,
    const float* __restrict__ lw3, const float* __restrict__ lb3,
    float* __restrict__ out)
{
    const int g = blockIdx.x, t = threadIdx.x;
    __shared__ float r[2 * H3];
    __shared__ float h1[HID];
    __shared__ float h2[HID / 2];
    for (int i = t; i < 2 * H3; i += 256) r[i] = g_readout[g * 2 * H3 + i];
    __syncthreads();
    {
        float a0 = 0.f, a1 = 0.f, a2 = 0.f, a3 = 0.f;
        for (int k = 0; k < 2 * H3; k += 4) {
            a0 += r[k + 0] * lw1[(size_t)(k + 0) * HID + t];
            a1 += r[k + 1] * lw1[(size_t)(k + 1) * HID + t];
            a2 += r[k + 2] * lw1[(size_t)(k + 2) * HID + t];
            a3 += r[k + 3] * lw1[(size_t)(k + 3) * HID + t];
        }
        h1[t] = fmaxf((a0 + a1) + (a2 + a3) + lb1[t], 0.f);
    }
    __syncthreads();
    if (t < 128) {
        float a0 = 0.f, a1 = 0.f;
        for (int k = 0; k < HID; k += 2) {
            a0 += h1[k + 0] * lw2[(size_t)(k + 0) * 128 + t];
            a1 += h1[k + 1] * lw2[(size_t)(k + 1) * 128 + t];
        }
        h2[t] = fmaxf(a0 + a1 + lb2[t], 0.f);
    }
    __syncthreads();
    if (t < 3) {
        float a = lb3[t];
        for (int k = 0; k < 128; k++) a += h2[k] * lw3[k * 3 + t];
        out[g * 3 + t] = a;
    }
}

// ---------------- launch ----------------
extern "C" void kernel_launch(void* const* d_in, const int* in_sizes, int n_in,
                              void* d_out, int out_size)
{
    // Resolve inputs by element count (robust to metadata ordering).
    // Unique sizes; the three 256-length biases are all zeros in this
    // problem so their relative order is irrelevant, but we keep it anyway.
    int ix = -1, iei = -1, iea = -1, iW1 = -1, iW2 = -1, ipw = -1;
    int ilw1 = -1, ilw2 = -1, ilb2 = -1, ilw3 = -1, ilb3 = -1;
    int b256[3] = {-1, -1, -1};
    int nb = 0;
    for (int i = 0; i < n_in; i++) {
        switch (in_sizes[i]) {
            case 25600000: ix   = i; break;   // x [50000,512]
            case 1600000:  iei  = i; break;   // edge_index [2,800000] int32
            case 800000:   iea  = i; break;   // edge_attr
            case 131072:   iW1  = i; break;   // W1 [512,256]
            case 65536:    iW2  = i; break;   // W2 [256,256]
            case 768:      ipw  = i; break;   // pw
            case 393216:   ilw1 = i; break;   // lw1 [1536,256]
            case 32768:    ilw2 = i; break;   // lw2 [256,128]
            case 128:      ilb2 = i; break;   // lb2
            case 384:      ilw3 = i; break;   // lw3 [128,3]
            case 3:        ilb3 = i; break;   // lb3
            case 256:      if (nb < 3) b256[nb++] = i; break; // b1, b2, lb1
            default: break;                    // batch (50000) unused
        }
    }

    const float* x   = (const float*)d_in[ix];
    const int*   ei  = (const int*)d_in[iei];     // int32 (JAX default)
    const float* ea  = (const float*)d_in[iea];
    const float* W1  = (const float*)d_in[iW1];
    const float* b1  = (const float*)d_in[b256[0]];
    const float* W2  = (const float*)d_in[iW2];
    const float* b2  = (const float*)d_in[b256[1]];
    const float* pw  = (const float*)d_in[ipw];
    const float* lw1 = (const float*)d_in[ilw1];
    const float* lb1 = (const float*)d_in[b256[2]];
    const float* lw2 = (const float*)d_in[ilw2];
    const float* lb2 = (const float*)d_in[ilb2];
    const float* lw3 = (const float*)d_in[ilw3];
    const float* lb3 = (const float*)d_in[ilb3];
    float* out = (float*)d_out;

    const int nb_nodes = (NNODES + 255) / 256;
    const int nb_edges = (NEDGES + 255) / 256;
    dim3 gemm_grid(HID / 128, (NNODES + 127) / 128);

    zero_kernel<<<nb_nodes, 256>>>();
    fill_kernel<<<nb_edges, 256>>>(ei, ea);
    dinv_kernel<<<nb_nodes, 256>>>();
    norm_kernel<<<nb_edges, 256>>>(ei, ea);

    sgemm_kernel<<<gemm_grid, 256>>>(x, 0, W1, CIN);
    agg_kernel<<<NNODES, 256>>>(b1, 1);

    sgemm_kernel<<<gemm_grid, 256>>>(x, 1, W2, HID);
    agg_kernel<<<NNODES, 256>>>(b2, 2);

    sgemm_kernel<<<gemm_grid, 256>>>(x, 2, W2, HID);
    agg_kernel<<<NNODES, 256>>>(b2, 3);

    pwnorm_kernel<<<1, 256>>>(pw);
    score_kernel<<<NNODES / 8, 256>>>(pw);
    radix_kernel<<<NGRAPH, 256>>>();
    selscale_kernel<<<NGRAPH, 256>>>();
    readout_kernel<<<NGRAPH * 3, 256>>>();
    mlp_kernel<<<NGRAPH, 256>>>(lw1, lb1, lw2, lb2, lw3, lb3, out);
}

// round 5
// speedup vs baseline: 1.7927x; 1.7927x over previous
#include <cuda_runtime.h>
#include <cuda_bf16.h>
#include <math.h>

// ---------------- problem constants ----------------
#define NNODES 50000
#define NEDGES 800000
#define NGRAPH 8
#define NPG    6250
#define CIN    512
#define HID    256
#define H3     768
#define KTOP   5000
#define CAP    96
#define NCHUNK 25          // ceil(6250/256)
#define RSLICE 25          // readout slices per (graph,layer); 250 nodes each

// ---------------- device scratch ----------------
__device__ __align__(256) float g_xw [NNODES * HID];
__device__ __align__(256) float g_x1 [NNODES * HID];
__device__ __align__(256) float g_x2 [NNODES * HID];
__device__ __align__(256) float g_x3 [NNODES * HID];
__device__ __align__(256) float g_deg[NNODES];
__device__ __align__(256) int   g_cnt[NNODES];
__device__ __align__(256) int   g_eperm[NNODES * CAP];
__device__ __align__(256) int   g_src [NEDGES];
__device__ __align__(256) float g_norm[NEDGES];
__device__ __align__(256) float g_sp  [3 * NNODES];   // per-layer score partials
__device__ __align__(256) float g_score[NNODES];
__device__ __align__(256) float g_sel  [NNODES];
__device__ unsigned g_thr[NGRAPH];
__device__ int      g_needeq[NGRAPH];
__device__ int g_eqcnt[NGRAPH * NCHUNK];
__device__ int g_eqoff[NGRAPH * NCHUNK];
__device__ __align__(256) float g_rsum[NGRAPH * 3 * RSLICE * HID];
__device__ __align__(256) float g_rmax[NGRAPH * 3 * RSLICE * HID];
__device__ __align__(256) float g_readout[NGRAPH * 2 * H3];
__device__ float g_pwinv;

__device__ __forceinline__ float* buf_select(int sel) {
    switch (sel) {
        case 0:  return g_xw;
        case 1:  return g_x1;
        case 2:  return g_x2;
        default: return g_x3;
    }
}

// ---------------- setup ----------------
__global__ void zero_kernel() {
    int i = blockIdx.x * 256 + threadIdx.x;
    if (i < NNODES) { g_deg[i] = 0.f; g_cnt[i] = 0; }
}

__global__ void fill_kernel(const int* __restrict__ ei,
                            const float* __restrict__ ea) {
    int e = blockIdx.x * 256 + threadIdx.x;
    if (e >= NEDGES) return;
    int s = ei[e];
    int d = ei[NEDGES + e];
    if ((unsigned)s >= NNODES || (unsigned)d >= NNODES) { g_src[e] = 0; return; }
    g_src[e] = s;
    atomicAdd(&g_deg[d], ea[e]);
    int slot = atomicAdd(&g_cnt[d], 1);
    if (slot < CAP) g_eperm[d * CAP + slot] = e;
}

__global__ void dinv_kernel() {
    int i = blockIdx.x * 256 + threadIdx.x;
    if (i < NNODES) g_deg[i] = rsqrtf(g_deg[i] + 1.0f);
}

__global__ void norm_kernel(const int* __restrict__ ei,
                            const float* __restrict__ ea) {
    int e = blockIdx.x * 256 + threadIdx.x;
    if (e >= NEDGES) return;
    int d = ei[NEDGES + e];
    if ((unsigned)d >= NNODES) { g_norm[e] = 0.f; return; }
    g_norm[e] = g_deg[g_src[e]] * ea[e] * g_deg[d];
}

// ---------------- SGEMM: g_xw[M,256] = A[M,K] @ B[K,256] ----------------
// 128x128x16 tiles, 256 threads, 8x8/thread, double-buffered smem.
#define BM 128
#define BN 128
#define BK 16
#define ASTRIDE 132   // padded; 132%4==0 keeps float4 alignment

__global__ __launch_bounds__(256, 2) void sgemm_kernel(
    const float* __restrict__ x_ext, int a_sel,
    const float* __restrict__ B, int K)
{
    const float* A = (a_sel == 0) ? x_ext : (const float*)buf_select(a_sel);
    float* C = g_xw;

    __shared__ __align__(16) float As[2][BK][ASTRIDE];
    __shared__ __align__(16) float Bs[2][BK][BN];

    const int tid = threadIdx.x;
    const int bm = blockIdx.y * BM;
    const int bn = blockIdx.x * BN;

    // A tile: 128 rows x 16 cols = 512 float4; thread handles f=tid and f=tid+256
    const int ar0 = tid >> 2;              // 0..63
    const int ar1 = ar0 + 64;              // 64..127
    const int ac  = (tid & 3) * 4;         // 0,4,8,12
    // B tile: 16 rows x 128 cols = 512 float4
    const int br0 = tid >> 5;              // 0..7
    const int br1 = br0 + 8;
    const int bc  = (tid & 31) * 4;

    const int tx = tid & 15, ty = tid >> 4;

    const bool ok0 = (bm + ar0) < NNODES;
    const bool ok1 = (bm + ar1) < NNODES;
    const float* Ap0 = A + (size_t)(bm + ar0) * K + ac;
    const float* Ap1 = A + (size_t)(bm + ar1) * K + ac;
    const float* Bp0 = B + (size_t)br0 * HID + bn + bc;
    const float* Bp1 = B + (size_t)br1 * HID + bn + bc;

    float acc[8][8];
#pragma unroll
    for (int i = 0; i < 8; i++)
#pragma unroll
        for (int j = 0; j < 8; j++) acc[i][j] = 0.f;

    float4 pa0, pa1, pb0, pb1;
    // prefetch tile 0
    pa0 = ok0 ? *(const float4*)(Ap0) : make_float4(0, 0, 0, 0);
    pa1 = ok1 ? *(const float4*)(Ap1) : make_float4(0, 0, 0, 0);
    pb0 = *(const float4*)(Bp0);
    pb1 = *(const float4*)(Bp1);
    // store tile 0
    As[0][ac + 0][ar0] = pa0.x; As[0][ac + 1][ar0] = pa0.y;
    As[0][ac + 2][ar0] = pa0.z; As[0][ac + 3][ar0] = pa0.w;
    As[0][ac + 0][ar1] = pa1.x; As[0][ac + 1][ar1] = pa1.y;
    As[0][ac + 2][ar1] = pa1.z; As[0][ac + 3][ar1] = pa1.w;
    *(float4*)&Bs[0][br0][bc] = pb0;
    *(float4*)&Bs[0][br1][bc] = pb1;
    __syncthreads();

    int buf = 0;
    for (int k0 = BK; k0 < K; k0 += BK) {
        // prefetch next tile
        pa0 = ok0 ? *(const float4*)(Ap0 + k0) : make_float4(0, 0, 0, 0);
        pa1 = ok1 ? *(const float4*)(Ap1 + k0) : make_float4(0, 0, 0, 0);
        pb0 = *(const float4*)(Bp0 + (size_t)k0 * HID);
        pb1 = *(const float4*)(Bp1 + (size_t)k0 * HID);

        // compute on current buffer
#pragma unroll
        for (int kk = 0; kk < BK; kk++) {
            float4 a0 = *(const float4*)&As[buf][kk][ty * 8];
            float4 a1 = *(const float4*)&As[buf][kk][ty * 8 + 4];
            float4 b0 = *(const float4*)&Bs[buf][kk][tx * 8];
            float4 b1 = *(const float4*)&Bs[buf][kk][tx * 8 + 4];
            float ra[8] = {a0.x, a0.y, a0.z, a0.w, a1.x, a1.y, a1.z, a1.w};
            float rb[8] = {b0.x, b0.y, b0.z, b0.w, b1.x, b1.y, b1.z, b1.w};
#pragma unroll
            for (int i = 0; i < 8; i++)
#pragma unroll
                for (int j = 0; j < 8; j++)
                    acc[i][j] += ra[i] * rb[j];
        }

        // store prefetched tile into other buffer
        int nb = buf ^ 1;
        As[nb][ac + 0][ar0] = pa0.x; As[nb][ac + 1][ar0] = pa0.y;
        As[nb][ac + 2][ar0] = pa0.z; As[nb][ac + 3][ar0] = pa0.w;
        As[nb][ac + 0][ar1] = pa1.x; As[nb][ac + 1][ar1] = pa1.y;
        As[nb][ac + 2][ar1] = pa1.z; As[nb][ac + 3][ar1] = pa1.w;
        *(float4*)&Bs[nb][br0][bc] = pb0;
        *(float4*)&Bs[nb][br1][bc] = pb1;
        __syncthreads();
        buf = nb;
    }

    // final tile
#pragma unroll
    for (int kk = 0; kk < BK; kk++) {
        float4 a0 = *(const float4*)&As[buf][kk][ty * 8];
        float4 a1 = *(const float4*)&As[buf][kk][ty * 8 + 4];
        float4 b0 = *(const float4*)&Bs[buf][kk][tx * 8];
        float4 b1 = *(const float4*)&Bs[buf][kk][tx * 8 + 4];
        float ra[8] = {a0.x, a0.y, a0.z, a0.w, a1.x, a1.y, a1.z, a1.w};
        float rb[8] = {b0.x, b0.y, b0.z, b0.w, b1.x, b1.y, b1.z, b1.w};
#pragma unroll
        for (int i = 0; i < 8; i++)
#pragma unroll
            for (int j = 0; j < 8; j++)
                acc[i][j] += ra[i] * rb[j];
    }

#pragma unroll
    for (int i = 0; i < 8; i++) {
        int row = bm + ty * 8 + i;
        if (row < NNODES) {
            *(float4*)&C[(size_t)row * HID + bn + tx * 8] =
                make_float4(acc[i][0], acc[i][1], acc[i][2], acc[i][3]);
            *(float4*)&C[(size_t)row * HID + bn + tx * 8 + 4] =
                make_float4(acc[i][4], acc[i][5], acc[i][6], acc[i][7]);
        }
    }
}

// ---------------- GCN aggregation + fused score partial ----------------
__global__ __launch_bounds__(256) void agg_kernel(
    const float* __restrict__ bias, int out_sel,
    const float* __restrict__ pwseg, int layer)
{
    const float* xw = g_xw;
    float* out = buf_select(out_sel);
    const int node = blockIdx.x;
    const int t = threadIdx.x;
    __shared__ int   s_src[CAP];
    __shared__ float s_nrm[CAP];
    __shared__ int   s_cnt;
    __shared__ float s_wsum[8];
    if (t == 0) { int c = g_cnt[node]; s_cnt = c < CAP ? c : CAP; }
    __syncthreads();
    const int cnt = s_cnt;
    if (t < cnt) {
        int e = g_eperm[node * CAP + t];
        s_src[t] = g_src[e];
        s_nrm[t] = g_norm[e];
    }
    __syncthreads();

    float d = g_deg[node];
    float acc = d * d * xw[(size_t)node * HID + t] + bias[t];
    int j = 0;
    for (; j + 4 <= cnt; j += 4) {
        float v0 = xw[(size_t)s_src[j + 0] * HID + t];
        float v1 = xw[(size_t)s_src[j + 1] * HID + t];
        float v2 = xw[(size_t)s_src[j + 2] * HID + t];
        float v3 = xw[(size_t)s_src[j + 3] * HID + t];
        acc += s_nrm[j + 0] * v0;
        acc += s_nrm[j + 1] * v1;
        acc += s_nrm[j + 2] * v2;
        acc += s_nrm[j + 3] * v3;
    }
    for (; j < cnt; j++)
        acc += s_nrm[j] * xw[(size_t)s_src[j] * HID + t];

    float v = fmaxf(acc, 0.f);
    out[(size_t)node * HID + t] = v;

    // fused score partial: dot(row, pwseg)
    float p = v * pwseg[t];
#pragma unroll
    for (int o = 16; o > 0; o >>= 1) p += __shfl_xor_sync(0xffffffffu, p, o);
    if ((t & 31) == 0) s_wsum[t >> 5] = p;
    __syncthreads();
    if (t == 0) {
        float s = 0.f;
#pragma unroll
        for (int w = 0; w < 8; w++) s += s_wsum[w];
        g_sp[layer * NNODES + node] = s;
    }
}

// ---------------- scoring ----------------
__global__ void pwnorm_kernel(const float* __restrict__ pw) {
    __shared__ float red[256];
    float s = 0.f;
    for (int i = threadIdx.x; i < H3; i += 256) s += pw[i] * pw[i];
    red[threadIdx.x] = s;
    __syncthreads();
    for (int o = 128; o > 0; o >>= 1) {
        if (threadIdx.x < o) red[threadIdx.x] += red[threadIdx.x + o];
        __syncthreads();
    }
    if (threadIdx.x == 0) g_pwinv = rsqrtf(red[0]);
}

__global__ void scorefin_kernel() {
    int i = blockIdx.x * 256 + threadIdx.x;
    if (i >= NNODES) return;
    float dot = g_sp[i] + g_sp[NNODES + i] + g_sp[2 * NNODES + i];
    g_score[i] = 1.f / (1.f + expf(-dot * g_pwinv));
}

// ---------------- exact top-K threshold per graph ----------------
__global__ void radix_kernel() {
    const int g = blockIdx.x;
    const float* sc = g_score + g * NPG;
    __shared__ int hist[256];
    __shared__ unsigned s_prefix;
    __shared__ int s_remaining;
    if (threadIdx.x == 0) { s_prefix = 0u; s_remaining = KTOP; }
    __syncthreads();
    for (int pass = 3; pass >= 0; --pass) {
        hist[threadIdx.x] = 0;
        __syncthreads();
        unsigned prefix = s_prefix;
        int shift = pass * 8;
        for (int i = threadIdx.x; i < NPG; i += 256) {
            unsigned bits = __float_as_uint(sc[i]);
            bool match = (pass == 3) || ((bits >> (shift + 8)) == prefix);
            if (match) atomicAdd(&hist[(bits >> shift) & 255u], 1);
        }
        __syncthreads();
        if (threadIdx.x == 0) {
            int rem = s_remaining;
            unsigned p = s_prefix;
            for (int b = 255; b >= 0; --b) {
                if (hist[b] >= rem) { s_prefix = (p << 8) | (unsigned)b; break; }
                rem -= hist[b];
            }
            s_remaining = rem;
        }
        __syncthreads();
    }
    if (threadIdx.x == 0) { g_thr[g] = s_prefix; g_needeq[g] = s_remaining; }
}

// ---- stable tie resolution, parallel (3 small kernels) ----
__global__ void eqcnt_kernel() {
    const int ch = blockIdx.x % NCHUNK;
    const int g  = blockIdx.x / NCHUNK;
    const unsigned thr = g_thr[g];
    int i = ch * 256 + threadIdx.x;
    bool eq = (i < NPG) && (__float_as_uint(g_score[g * NPG + i]) == thr);
    unsigned bal = __ballot_sync(0xffffffffu, eq);
    __shared__ int wcnt[8];
    if ((threadIdx.x & 31) == 0) wcnt[threadIdx.x >> 5] = __popc(bal);
    __syncthreads();
    if (threadIdx.x == 0) {
        int s = 0;
#pragma unroll
        for (int w = 0; w < 8; w++) s += wcnt[w];
        g_eqcnt[g * NCHUNK + ch] = s;
    }
}

__global__ void eqscan_kernel() {
    const int g = blockIdx.x;
    if (threadIdx.x == 0) {
        int run = 0;
        for (int c = 0; c < NCHUNK; c++) {
            g_eqoff[g * NCHUNK + c] = run;
            run += g_eqcnt[g * NCHUNK + c];
        }
    }
}

__global__ void mark_kernel() {
    const int ch = blockIdx.x % NCHUNK;
    const int g  = blockIdx.x / NCHUNK;
    const unsigned thr = g_thr[g];
    const int need = g_needeq[g];
    int i = ch * 256 + threadIdx.x;
    float s = 0.f; unsigned bits = 0u;
    if (i < NPG) { s = g_score[g * NPG + i]; bits = __float_as_uint(s); }
    bool eq = (i < NPG) && (bits == thr);
    unsigned bal = __ballot_sync(0xffffffffu, eq);
    int lane = threadIdx.x & 31, warp = threadIdx.x >> 5;
    int lr = __popc(bal & ((1u << lane) - 1u));
    __shared__ int wcnt[8], woff[8];
    if (lane == 0) wcnt[warp] = __popc(bal);
    __syncthreads();
    if (threadIdx.x == 0) {
        int run = 0;
#pragma unroll
        for (int w = 0; w < 8; w++) { woff[w] = run; run += wcnt[w]; }
    }
    __syncthreads();
    if (i < NPG) {
        float out = 0.f;
        if (bits > thr) out = s;
        else if (eq) {
            int rank = g_eqoff[g * NCHUNK + ch] + woff[warp] + lr;
            if (rank < need) out = s;
        }
        g_sel[g * NPG + i] = out;
    }
}

// ---------------- readout, 2-stage ----------------
__global__ __launch_bounds__(256) void readout1_kernel() {
    const int sl = blockIdx.x % RSLICE;
    const int c  = (blockIdx.x / RSLICE) % 3;
    const int g  = blockIdx.x / (RSLICE * 3);
    const float* X = (c == 0) ? g_x1 : ((c == 1) ? g_x2 : g_x3);
    const int f = threadIdx.x;
    const float* sel = g_sel + g * NPG;
    const size_t rowbase = (size_t)g * NPG * HID;
    const int n0 = sl * (NPG / RSLICE), n1 = n0 + NPG / RSLICE;
    float sum0 = 0.f, sum1 = 0.f, mx = 0.f;
    for (int i = n0; i < n1; i += 2) {
        float v0 = sel[i]     * X[rowbase + (size_t)i * HID + f];
        float v1 = sel[i + 1] * X[rowbase + (size_t)(i + 1) * HID + f];
        sum0 += v0; sum1 += v1;
        mx = fmaxf(mx, fmaxf(v0, v1));
    }
    g_rsum[(size_t)blockIdx.x * HID + f] = sum0 + sum1;
    g_rmax[(size_t)blockIdx.x * HID + f] = mx;
}

__global__ __launch_bounds__(256) void readout2_kernel() {
    const int c = blockIdx.x % 3, g = blockIdx.x / 3;
    const int f = threadIdx.x;
    const int base = (g * 3 + c) * RSLICE;
    float sum = 0.f, mx = 0.f;
    for (int k = 0; k < RSLICE; k++) {
        sum += g_rsum[(size_t)(base + k) * HID + f];
        mx = fmaxf(mx, g_rmax[(size_t)(base + k) * HID + f]);
    }
    g_readout[g * 2 * H3 + c * HID + f]      = sum * (1.f / (float)KTOP);
    g_readout[g * 2 * H3 + H3 + c * HID + f] = mx;
}

// ---------------- final MLP ----------------
__global__ __launch_bounds__(256) void mlp_kernel(
    const float* __restrict__ lw1, const float* __restrict__ lb1,
    const float* __restrict__ lw2, const float* __restrict__ lb2,
    const float* __restrict__ lw3, const float* __restrict__ lb3,
    float* __restrict__ out)
{
    const int g = blockIdx.x, t = threadIdx.x;
    __shared__ float r[2 * H3];
    __shared__ float h1[HID];
    __shared__ float h2[HID / 2];
    for (int i = t; i < 2 * H3; i += 256) r[i] = g_readout[g * 2 * H3 + i];
    __syncthreads();
    {
        float a0 = 0.f, a1 = 0.f, a2 = 0.f, a3 = 0.f;
        for (int k = 0; k < 2 * H3; k += 4) {
            a0 += r[k + 0] * lw1[(size_t)(k + 0) * HID + t];
            a1 += r[k + 1] * lw1[(size_t)(k + 1) * HID + t];
            a2 += r[k + 2] * lw1[(size_t)(k + 2) * HID + t];
            a3 += r[k + 3] * lw1[(size_t)(k + 3) * HID + t];
        }
        h1[t] = fmaxf((a0 + a1) + (a2 + a3) + lb1[t], 0.f);
    }
    __syncthreads();
    if (t < 128) {
        float a0 = 0.f, a1 = 0.f;
        for (int k = 0; k < HID; k += 2) {
            a0 += h1[k + 0] * lw2[(size_t)(k + 0) * 128 + t];
            a1 += h1[k + 1] * lw2[(size_t)(k + 1) * 128 + t];
        }
        h2[t] = fmaxf(a0 + a1 + lb2[t], 0.f);
    }
    __syncthreads();
    if (t < 3) {
        float a = lb3[t];
        for (int k = 0; k < 128; k++) a += h2[k] * lw3[k * 3 + t];
        out[g * 3 + t] = a;
    }
}

// ---------------- launch ----------------
extern "C" void kernel_launch(void* const* d_in, const int* in_sizes, int n_in,
                              void* d_out, int out_size)
{
    int ix = -1, iei = -1, iea = -1, iW1 = -1, iW2 = -1, ipw = -1;
    int ilw1 = -1, ilw2 = -1, ilb2 = -1, ilw3 = -1, ilb3 = -1;
    int b256[3] = {-1, -1, -1};
    int nb = 0;
    for (int i = 0; i < n_in; i++) {
        switch (in_sizes[i]) {
            case 25600000: ix   = i; break;
            case 1600000:  iei  = i; break;
            case 800000:   iea  = i; break;
            case 131072:   iW1  = i; break;
            case 65536:    iW2  = i; break;
            case 768:      ipw  = i; break;
            case 393216:   ilw1 = i; break;
            case 32768:    ilw2 = i; break;
            case 128:      ilb2 = i; break;
            case 384:      ilw3 = i; break;
            case 3:        ilb3 = i; break;
            case 256:      if (nb < 3) b256[nb++] = i; break;
            default: break;
        }
    }

    const float* x   = (const float*)d_in[ix];
    const int*   ei  = (const int*)d_in[iei];
    const float* ea  = (const float*)d_in[iea];
    const float* W1  = (const float*)d_in[iW1];
    const float* b1  = (const float*)d_in[b256[0]];
    const float* W2  = (const float*)d_in[iW2];
    const float* b2  = (const float*)d_in[b256[1]];
    const float* pw  = (const float*)d_in[ipw];
    const float* lw1 = (const float*)d_in[ilw1];
    const float* lb1 = (const float*)d_in[b256[2]];
    const float* lw2 = (const float*)d_in[ilw2];
    const float* lb2 = (const float*)d_in[ilb2];
    const float* lw3 = (const float*)d_in[ilw3];
    const float* lb3 = (const float*)d_in[ilb3];
    float* out = (float*)d_out;

    const int nb_nodes = (NNODES + 255) / 256;
    const int nb_edges = (NEDGES + 255) / 256;
    dim3 gemm_grid(HID / BN, (NNODES + BM - 1) / BM);

    zero_kernel<<<nb_nodes, 256>>>();
    fill_kernel<<<nb_edges, 256>>>(ei, ea);
    dinv_kernel<<<nb_nodes, 256>>>();
    norm_kernel<<<nb_edges, 256>>>(ei, ea);

    sgemm_kernel<<<gemm_grid, 256>>>(x, 0, W1, CIN);
    agg_kernel<<<NNODES, 256>>>(b1, 1, pw, 0);

    sgemm_kernel<<<gemm_grid, 256>>>(x, 1, W2, HID);
    agg_kernel<<<NNODES, 256>>>(b2, 2, pw + HID, 1);

    sgemm_kernel<<<gemm_grid, 256>>>(x, 2, W2, HID);
    agg_kernel<<<NNODES, 256>>>(b2, 3, pw + 2 * HID, 2);

    pwnorm_kernel<<<1, 256>>>(pw);
    scorefin_kernel<<<nb_nodes, 256>>>();
    radix_kernel<<<NGRAPH, 256>>>();
    eqcnt_kernel<<<NGRAPH * NCHUNK, 256>>>();
    eqscan_kernel<<<NGRAPH, 32>>>();
    mark_kernel<<<NGRAPH * NCHUNK, 256>>>();
    readout1_kernel<<<NGRAPH * 3 * RSLICE, 256>>>();
    readout2_kernel<<<NGRAPH * 3, 256>>>();
    mlp_kernel<<<NGRAPH, 256>>>(lw1, lb1, lw2, lb2, lw3, lb3, out);
}

// round 6
// speedup vs baseline: 1.9255x; 1.0741x over previous
#include <cuda_runtime.h>
#include <cuda_bf16.h>
#include <math.h>

// ---------------- problem constants ----------------
#define NNODES 50000
#define NEDGES 800000
#define NGRAPH 8
#define NPG    6250
#define CIN    512
#define HID    256
#define H3     768
#define KTOP   5000
#define CAP    96
#define NCHUNK 25
#define RSLICE 25

// ---------------- device scratch ----------------
__device__ __align__(256) float g_xw [NNODES * HID];
__device__ __align__(256) float g_x1 [NNODES * HID];
__device__ __align__(256) float g_x2 [NNODES * HID];
__device__ __align__(256) float g_x3 [NNODES * HID];
__device__ __align__(256) float g_deg[NNODES];
__device__ __align__(256) int   g_cnt[NNODES];
__device__ __align__(256) int   g_eperm[NNODES * CAP];
__device__ __align__(256) int   g_src [NEDGES];
__device__ __align__(256) float g_norm[NEDGES];
__device__ __align__(256) float g_sp  [3 * NNODES];
__device__ __align__(256) float g_score[NNODES];
__device__ __align__(256) float g_sel  [NNODES];
__device__ unsigned g_thr[NGRAPH];
__device__ int      g_needeq[NGRAPH];
__device__ int g_eqcnt[NGRAPH * NCHUNK];
__device__ int g_eqoff[NGRAPH * NCHUNK];
__device__ __align__(256) float g_rsum[NGRAPH * 3 * RSLICE * HID];
__device__ __align__(256) float g_rmax[NGRAPH * 3 * RSLICE * HID];
__device__ __align__(256) float g_readout[NGRAPH * 2 * H3];
__device__ float g_pwinv;
// bf16 hi/lo splits of the weights
__device__ __align__(256) __nv_bfloat16 g_w1h[CIN * HID];
__device__ __align__(256) __nv_bfloat16 g_w1l[CIN * HID];
__device__ __align__(256) __nv_bfloat16 g_w2h[HID * HID];
__device__ __align__(256) __nv_bfloat16 g_w2l[HID * HID];

__device__ __forceinline__ float* buf_select(int sel) {
    switch (sel) {
        case 0:  return g_xw;
        case 1:  return g_x1;
        case 2:  return g_x2;
        default: return g_x3;
    }
}

// ---------------- setup ----------------
__global__ void zero_kernel() {
    int i = blockIdx.x * 256 + threadIdx.x;
    if (i < NNODES) { g_deg[i] = 0.f; g_cnt[i] = 0; }
}

__global__ void fill_kernel(const int* __restrict__ ei,
                            const float* __restrict__ ea) {
    int e = blockIdx.x * 256 + threadIdx.x;
    if (e >= NEDGES) return;
    int s = ei[e];
    int d = ei[NEDGES + e];
    if ((unsigned)s >= NNODES || (unsigned)d >= NNODES) { g_src[e] = 0; return; }
    g_src[e] = s;
    atomicAdd(&g_deg[d], ea[e]);
    int slot = atomicAdd(&g_cnt[d], 1);
    if (slot < CAP) g_eperm[d * CAP + slot] = e;
}

__global__ void dinv_kernel() {
    int i = blockIdx.x * 256 + threadIdx.x;
    if (i < NNODES) g_deg[i] = rsqrtf(g_deg[i] + 1.0f);
}

__global__ void norm_kernel(const int* __restrict__ ei,
                            const float* __restrict__ ea) {
    int e = blockIdx.x * 256 + threadIdx.x;
    if (e >= NEDGES) return;
    int d = ei[NEDGES + e];
    if ((unsigned)d >= NNODES) { g_norm[e] = 0.f; return; }
    g_norm[e] = g_deg[g_src[e]] * ea[e] * g_deg[d];
}

// split weights into bf16 hi + lo (which: 0 -> w1, 1 -> w2)
__global__ void splitw_kernel(const float* __restrict__ W, int n, int which) {
    int i = blockIdx.x * 256 + threadIdx.x;
    if (i >= n) return;
    __nv_bfloat16* hi = (which == 0) ? g_w1h : g_w2h;
    __nv_bfloat16* lo = (which == 0) ? g_w1l : g_w2l;
    float w = W[i];
    __nv_bfloat16 h = __float2bfloat16(w);
    float r = w - __bfloat162float(h);
    hi[i] = h;
    lo[i] = __float2bfloat16(r);
}

// ---------------- bf16x3 tensor-core GEMM ----------------
// C[M,256] = A[M,K] @ B[K,256] with A,B split into bf16 hi/lo;
// D += Ah*Bh + Ah*Bl + Al*Bh  (error ~2^-18).
// Block tile 128x64, BK=32 bf16, 8 warps of 32x32, mma.m16n8k16.
#define GBM 128
#define GBN 64
#define GBK 32
#define KPAD 34

__device__ __forceinline__ void mma_bf16(float* d, const unsigned* a, const unsigned* b) {
    asm volatile(
        "mma.sync.aligned.m16n8k16.row.col.f32.bf16.bf16.f32 "
        "{%0,%1,%2,%3}, {%4,%5,%6,%7}, {%8,%9}, {%0,%1,%2,%3};\n"
        : "+f"(d[0]), "+f"(d[1]), "+f"(d[2]), "+f"(d[3])
        : "r"(a[0]), "r"(a[1]), "r"(a[2]), "r"(a[3]), "r"(b[0]), "r"(b[1]));
}

__global__ __launch_bounds__(256, 2) void bgemm_kernel(
    const float* __restrict__ x_ext, int a_sel, int wsel, int K)
{
    const float* A = (a_sel == 0) ? x_ext : (const float*)buf_select(a_sel);
    const __nv_bfloat16* Bh = (wsel == 0) ? g_w1h : g_w2h;
    const __nv_bfloat16* Bl = (wsel == 0) ? g_w1l : g_w2l;
    float* C = g_xw;

    __shared__ __nv_bfloat16 Ash[GBM][KPAD];
    __shared__ __nv_bfloat16 Asl[GBM][KPAD];
    __shared__ __nv_bfloat16 Bsh[GBN][KPAD];
    __shared__ __nv_bfloat16 Bsl[GBN][KPAD];

    const int tid = threadIdx.x;
    const int bm = blockIdx.y * GBM;
    const int bn = blockIdx.x * GBN;

    const int lane = tid & 31;
    const int warp = tid >> 5;
    const int wm = warp >> 1;      // 0..3 -> 32 rows each
    const int wn = warp & 1;       // 0..1 -> 32 cols each
    const int lrow = lane >> 2;    // 0..7
    const int lq   = lane & 3;     // 0..3

    // A loader: thread handles row (tid>>1), 16 f32 starting at (tid&1)*16
    const int a_row = tid >> 1;
    const int a_c0  = (tid & 1) * 16;
    const bool a_ok = (bm + a_row) < NNODES;
    const float* Aptr = A + (size_t)(bm + a_row) * K + a_c0;
    // B loader: thread handles k = tid>>3, 8 bf16 at n0 = (tid&7)*8
    const int b_k  = tid >> 3;
    const int b_n0 = (tid & 7) * 8;

    float d[2][4][4];
#pragma unroll
    for (int i = 0; i < 2; i++)
#pragma unroll
        for (int j = 0; j < 4; j++)
#pragma unroll
            for (int r = 0; r < 4; r++) d[i][j][r] = 0.f;

    for (int k0 = 0; k0 < K; k0 += GBK) {
        // -------- global loads into registers --------
        float4 av[4];
#pragma unroll
        for (int v = 0; v < 4; v++)
            av[v] = a_ok ? *(const float4*)(Aptr + k0 + v * 4)
                         : make_float4(0.f, 0.f, 0.f, 0.f);
        __nv_bfloat16 bhv[8], blv[8];
        {
            const __nv_bfloat16* p = Bh + (size_t)(k0 + b_k) * HID + bn + b_n0;
            *(uint4*)bhv = *(const uint4*)p;
            const __nv_bfloat16* q = Bl + (size_t)(k0 + b_k) * HID + bn + b_n0;
            *(uint4*)blv = *(const uint4*)q;
        }
        __syncthreads();   // previous compute done before overwriting smem
        // -------- store A split --------
#pragma unroll
        for (int v = 0; v < 4; v++) {
            float vv[4] = {av[v].x, av[v].y, av[v].z, av[v].w};
#pragma unroll
            for (int j = 0; j < 4; j++) {
                float f = vv[j];
                __nv_bfloat16 h = __float2bfloat16(f);
                float r = f - __bfloat162float(h);
                Ash[a_row][a_c0 + v * 4 + j] = h;
                Asl[a_row][a_c0 + v * 4 + j] = __float2bfloat16(r);
            }
        }
        // -------- store B transposed --------
#pragma unroll
        for (int j = 0; j < 8; j++) {
            Bsh[b_n0 + j][b_k] = bhv[j];
            Bsl[b_n0 + j][b_k] = blv[j];
        }
        __syncthreads();
        // -------- compute --------
#pragma unroll
        for (int ks = 0; ks < GBK; ks += 16) {
            unsigned ah[2][4], al[2][4], bh[4][2], bl[4][2];
#pragma unroll
            for (int fm = 0; fm < 2; fm++) {
                int m = wm * 32 + fm * 16 + lrow;
                int kc = ks + 2 * lq;
                ah[fm][0] = *(const unsigned*)&Ash[m][kc];
                ah[fm][1] = *(const unsigned*)&Ash[m + 8][kc];
                ah[fm][2] = *(const unsigned*)&Ash[m][kc + 8];
                ah[fm][3] = *(const unsigned*)&Ash[m + 8][kc + 8];
                al[fm][0] = *(const unsigned*)&Asl[m][kc];
                al[fm][1] = *(const unsigned*)&Asl[m + 8][kc];
                al[fm][2] = *(const unsigned*)&Asl[m][kc + 8];
                al[fm][3] = *(const unsigned*)&Asl[m + 8][kc + 8];
            }
#pragma unroll
            for (int fn = 0; fn < 4; fn++) {
                int n = wn * 32 + fn * 8 + lrow;
                int kc = ks + 2 * lq;
                bh[fn][0] = *(const unsigned*)&Bsh[n][kc];
                bh[fn][1] = *(const unsigned*)&Bsh[n][kc + 8];
                bl[fn][0] = *(const unsigned*)&Bsl[n][kc];
                bl[fn][1] = *(const unsigned*)&Bsl[n][kc + 8];
            }
#pragma unroll
            for (int fm = 0; fm < 2; fm++)
#pragma unroll
                for (int fn = 0; fn < 4; fn++) {
                    mma_bf16(d[fm][fn], ah[fm], bh[fn]);
                    mma_bf16(d[fm][fn], ah[fm], bl[fn]);
                    mma_bf16(d[fm][fn], al[fm], bh[fn]);
                }
        }
    }

    // -------- epilogue --------
#pragma unroll
    for (int fm = 0; fm < 2; fm++) {
#pragma unroll
        for (int fn = 0; fn < 4; fn++) {
            int row = bm + wm * 32 + fm * 16 + lrow;
            int col = bn + wn * 32 + fn * 8 + 2 * lq;
            if (row < NNODES)
                *(float2*)&C[(size_t)row * HID + col] =
                    make_float2(d[fm][fn][0], d[fm][fn][1]);
            if (row + 8 < NNODES)
                *(float2*)&C[(size_t)(row + 8) * HID + col] =
                    make_float2(d[fm][fn][2], d[fm][fn][3]);
        }
    }
}

// ---------------- GCN aggregation + fused score partial ----------------
__global__ __launch_bounds__(256) void agg_kernel(
    const float* __restrict__ bias, int out_sel,
    const float* __restrict__ pwseg, int layer)
{
    const float* xw = g_xw;
    float* out = buf_select(out_sel);
    const int node = blockIdx.x;
    const int t = threadIdx.x;
    __shared__ int   s_src[CAP];
    __shared__ float s_nrm[CAP];
    __shared__ int   s_cnt;
    __shared__ float s_wsum[8];
    if (t == 0) { int c = g_cnt[node]; s_cnt = c < CAP ? c : CAP; }
    __syncthreads();
    const int cnt = s_cnt;
    if (t < cnt) {
        int e = g_eperm[node * CAP + t];
        s_src[t] = g_src[e];
        s_nrm[t] = g_norm[e];
    }
    __syncthreads();

    float d = g_deg[node];
    float acc = d * d * xw[(size_t)node * HID + t] + bias[t];
    int j = 0;
    for (; j + 4 <= cnt; j += 4) {
        float v0 = xw[(size_t)s_src[j + 0] * HID + t];
        float v1 = xw[(size_t)s_src[j + 1] * HID + t];
        float v2 = xw[(size_t)s_src[j + 2] * HID + t];
        float v3 = xw[(size_t)s_src[j + 3] * HID + t];
        acc += s_nrm[j + 0] * v0;
        acc += s_nrm[j + 1] * v1;
        acc += s_nrm[j + 2] * v2;
        acc += s_nrm[j + 3] * v3;
    }
    for (; j < cnt; j++)
        acc += s_nrm[j] * xw[(size_t)s_src[j] * HID + t];

    float v = fmaxf(acc, 0.f);
    out[(size_t)node * HID + t] = v;

    float p = v * pwseg[t];
#pragma unroll
    for (int o = 16; o > 0; o >>= 1) p += __shfl_xor_sync(0xffffffffu, p, o);
    if ((t & 31) == 0) s_wsum[t >> 5] = p;
    __syncthreads();
    if (t == 0) {
        float s = 0.f;
#pragma unroll
        for (int w = 0; w < 8; w++) s += s_wsum[w];
        g_sp[layer * NNODES + node] = s;
    }
}

// ---------------- scoring ----------------
__global__ void pwnorm_kernel(const float* __restrict__ pw) {
    __shared__ float red[256];
    float s = 0.f;
    for (int i = threadIdx.x; i < H3; i += 256) s += pw[i] * pw[i];
    red[threadIdx.x] = s;
    __syncthreads();
    for (int o = 128; o > 0; o >>= 1) {
        if (threadIdx.x < o) red[threadIdx.x] += red[threadIdx.x + o];
        __syncthreads();
    }
    if (threadIdx.x == 0) g_pwinv = rsqrtf(red[0]);
}

__global__ void scorefin_kernel() {
    int i = blockIdx.x * 256 + threadIdx.x;
    if (i >= NNODES) return;
    float dot = g_sp[i] + g_sp[NNODES + i] + g_sp[2 * NNODES + i];
    g_score[i] = 1.f / (1.f + expf(-dot * g_pwinv));
}

// ---------------- exact top-K threshold per graph ----------------
__global__ void radix_kernel() {
    const int g = blockIdx.x;
    const float* sc = g_score + g * NPG;
    __shared__ int hist[256];
    __shared__ unsigned s_prefix;
    __shared__ int s_remaining;
    if (threadIdx.x == 0) { s_prefix = 0u; s_remaining = KTOP; }
    __syncthreads();
    for (int pass = 3; pass >= 0; --pass) {
        hist[threadIdx.x] = 0;
        __syncthreads();
        unsigned prefix = s_prefix;
        int shift = pass * 8;
        for (int i = threadIdx.x; i < NPG; i += 256) {
            unsigned bits = __float_as_uint(sc[i]);
            bool match = (pass == 3) || ((bits >> (shift + 8)) == prefix);
            if (match) atomicAdd(&hist[(bits >> shift) & 255u], 1);
        }
        __syncthreads();
        if (threadIdx.x == 0) {
            int rem = s_remaining;
            unsigned p = s_prefix;
            for (int b = 255; b >= 0; --b) {
                if (hist[b] >= rem) { s_prefix = (p << 8) | (unsigned)b; break; }
                rem -= hist[b];
            }
            s_remaining = rem;
        }
        __syncthreads();
    }
    if (threadIdx.x == 0) { g_thr[g] = s_prefix; g_needeq[g] = s_remaining; }
}

// ---- stable tie resolution, parallel ----
__global__ void eqcnt_kernel() {
    const int ch = blockIdx.x % NCHUNK;
    const int g  = blockIdx.x / NCHUNK;
    const unsigned thr = g_thr[g];
    int i = ch * 256 + threadIdx.x;
    bool eq = (i < NPG) && (__float_as_uint(g_score[g * NPG + i]) == thr);
    unsigned bal = __ballot_sync(0xffffffffu, eq);
    __shared__ int wcnt[8];
    if ((threadIdx.x & 31) == 0) wcnt[threadIdx.x >> 5] = __popc(bal);
    __syncthreads();
    if (threadIdx.x == 0) {
        int s = 0;
#pragma unroll
        for (int w = 0; w < 8; w++) s += wcnt[w];
        g_eqcnt[g * NCHUNK + ch] = s;
    }
}

__global__ void eqscan_kernel() {
    const int g = blockIdx.x;
    if (threadIdx.x == 0) {
        int run = 0;
        for (int c = 0; c < NCHUNK; c++) {
            g_eqoff[g * NCHUNK + c] = run;
            run += g_eqcnt[g * NCHUNK + c];
        }
    }
}

__global__ void mark_kernel() {
    const int ch = blockIdx.x % NCHUNK;
    const int g  = blockIdx.x / NCHUNK;
    const unsigned thr = g_thr[g];
    const int need = g_needeq[g];
    int i = ch * 256 + threadIdx.x;
    float s = 0.f; unsigned bits = 0u;
    if (i < NPG) { s = g_score[g * NPG + i]; bits = __float_as_uint(s); }
    bool eq = (i < NPG) && (bits == thr);
    unsigned bal = __ballot_sync(0xffffffffu, eq);
    int lane = threadIdx.x & 31, warp = threadIdx.x >> 5;
    int lr = __popc(bal & ((1u << lane) - 1u));
    __shared__ int wcnt[8], woff[8];
    if (lane == 0) wcnt[warp] = __popc(bal);
    __syncthreads();
    if (threadIdx.x == 0) {
        int run = 0;
#pragma unroll
        for (int w = 0; w < 8; w++) { woff[w] = run; run += wcnt[w]; }
    }
    __syncthreads();
    if (i < NPG) {
        float out = 0.f;
        if (bits > thr) out = s;
        else if (eq) {
            int rank = g_eqoff[g * NCHUNK + ch] + woff[warp] + lr;
            if (rank < need) out = s;
        }
        g_sel[g * NPG + i] = out;
    }
}

// ---------------- readout, 2-stage ----------------
__global__ __launch_bounds__(256) void readout1_kernel() {
    const int sl = blockIdx.x % RSLICE;
    const int c  = (blockIdx.x / RSLICE) % 3;
    const int g  = blockIdx.x / (RSLICE * 3);
    const float* X = (c == 0) ? g_x1 : ((c == 1) ? g_x2 : g_x3);
    const int f = threadIdx.x;
    const float* sel = g_sel + g * NPG;
    const size_t rowbase = (size_t)g * NPG * HID;
    const int n0 = sl * (NPG / RSLICE), n1 = n0 + NPG / RSLICE;
    float sum0 = 0.f, sum1 = 0.f, mx = 0.f;
    for (int i = n0; i < n1; i += 2) {
        float v0 = sel[i]     * X[rowbase + (size_t)i * HID + f];
        float v1 = sel[i + 1] * X[rowbase + (size_t)(i + 1) * HID + f];
        sum0 += v0; sum1 += v1;
        mx = fmaxf(mx, fmaxf(v0, v1));
    }
    g_rsum[(size_t)blockIdx.x * HID + f] = sum0 + sum1;
    g_rmax[(size_t)blockIdx.x * HID + f] = mx;
}

__global__ __launch_bounds__(256) void readout2_kernel() {
    const int c = blockIdx.x % 3, g = blockIdx.x / 3;
    const int f = threadIdx.x;
    const int base = (g * 3 + c) * RSLICE;
    float sum = 0.f, mx = 0.f;
    for (int k = 0; k < RSLICE; k++) {
        sum += g_rsum[(size_t)(base + k) * HID + f];
        mx = fmaxf(mx, g_rmax[(size_t)(base + k) * HID + f]);
    }
    g_readout[g * 2 * H3 + c * HID + f]      = sum * (1.f / (float)KTOP);
    g_readout[g * 2 * H3 + H3 + c * HID + f] = mx;
}

// ---------------- final MLP ----------------
__global__ __launch_bounds__(256) void mlp_kernel(
    const float* __restrict__ lw1, const float* __restrict__ lb1,
    const float* __restrict__ lw2, const float* __restrict__ lb2,
    const float* __restrict__ lw3, const float* __restrict__ lb3,
    float* __restrict__ out)
{
    const int g = blockIdx.x, t = threadIdx.x;
    __shared__ float r[2 * H3];
    __shared__ float h1[HID];
    __shared__ float h2[HID / 2];
    for (int i = t; i < 2 * H3; i += 256) r[i] = g_readout[g * 2 * H3 + i];
    __syncthreads();
    {
        float a0 = 0.f, a1 = 0.f, a2 = 0.f, a3 = 0.f;
        for (int k = 0; k < 2 * H3; k += 4) {
            a0 += r[k + 0] * lw1[(size_t)(k + 0) * HID + t];
            a1 += r[k + 1] * lw1[(size_t)(k + 1) * HID + t];
            a2 += r[k + 2] * lw1[(size_t)(k + 2) * HID + t];
            a3 += r[k + 3] * lw1[(size_t)(k + 3) * HID + t];
        }
        h1[t] = fmaxf((a0 + a1) + (a2 + a3) + lb1[t], 0.f);
    }
    __syncthreads();
    if (t < 128) {
        float a0 = 0.f, a1 = 0.f;
        for (int k = 0; k < HID; k += 2) {
            a0 += h1[k + 0] * lw2[(size_t)(k + 0) * 128 + t];
            a1 += h1[k + 1] * lw2[(size_t)(k + 1) * 128 + t];
        }
        h2[t] = fmaxf(a0 + a1 + lb2[t], 0.f);
    }
    __syncthreads();
    if (t < 3) {
        float a = lb3[t];
        for (int k = 0; k < 128; k++) a += h2[k] * lw3[k * 3 + t];
        out[g * 3 + t] = a;
    }
}

// ---------------- launch ----------------
extern "C" void kernel_launch(void* const* d_in, const int* in_sizes, int n_in,
                              void* d_out, int out_size)
{
    int ix = -1, iei = -1, iea = -1, iW1 = -1, iW2 = -1, ipw = -1;
    int ilw1 = -1, ilw2 = -1, ilb2 = -1, ilw3 = -1, ilb3 = -1;
    int b256[3] = {-1, -1, -1};
    int nb = 0;
    for (int i = 0; i < n_in; i++) {
        switch (in_sizes[i]) {
            case 25600000: ix   = i; break;
            case 1600000:  iei  = i; break;
            case 800000:   iea  = i; break;
            case 131072:   iW1  = i; break;
            case 65536:    iW2  = i; break;
            case 768:      ipw  = i; break;
            case 393216:   ilw1 = i; break;
            case 32768:    ilw2 = i; break;
            case 128:      ilb2 = i; break;
            case 384:      ilw3 = i; break;
            case 3:        ilb3 = i; break;
            case 256:      if (nb < 3) b256[nb++] = i; break;
            default: break;
        }
    }

    const float* x   = (const float*)d_in[ix];
    const int*   ei  = (const int*)d_in[iei];
    const float* ea  = (const float*)d_in[iea];
    const float* W1  = (const float*)d_in[iW1];
    const float* b1  = (const float*)d_in[b256[0]];
    const float* W2  = (const float*)d_in[iW2];
    const float* b2  = (const float*)d_in[b256[1]];
    const float* pw  = (const float*)d_in[ipw];
    const float* lw1 = (const float*)d_in[ilw1];
    const float* lb1 = (const float*)d_in[b256[2]];
    const float* lw2 = (const float*)d_in[ilw2];
    const float* lb2 = (const float*)d_in[ilb2];
    const float* lw3 = (const float*)d_in[ilw3];
    const float* lb3 = (const float*)d_in[ilb3];
    float* out = (float*)d_out;

    const int nb_nodes = (NNODES + 255) / 256;
    const int nb_edges = (NEDGES + 255) / 256;
    dim3 gemm_grid(HID / GBN, (NNODES + GBM - 1) / GBM);

    zero_kernel<<<nb_nodes, 256>>>();
    fill_kernel<<<nb_edges, 256>>>(ei, ea);
    splitw_kernel<<<(CIN * HID + 255) / 256, 256>>>(W1, CIN * HID, 0);
    splitw_kernel<<<(HID * HID + 255) / 256, 256>>>(W2, HID * HID, 1);
    dinv_kernel<<<nb_nodes, 256>>>();
    norm_kernel<<<nb_edges, 256>>>(ei, ea);

    bgemm_kernel<<<gemm_grid, 256>>>(x, 0, 0, CIN);
    agg_kernel<<<NNODES, 256>>>(b1, 1, pw, 0);

    bgemm_kernel<<<gemm_grid, 256>>>(x, 1, 1, HID);
    agg_kernel<<<NNODES, 256>>>(b2, 2, pw + HID, 1);

    bgemm_kernel<<<gemm_grid, 256>>>(x, 2, 1, HID);
    agg_kernel<<<NNODES, 256>>>(b2, 3, pw + 2 * HID, 2);

    pwnorm_kernel<<<1, 256>>>(pw);
    scorefin_kernel<<<nb_nodes, 256>>>();
    radix_kernel<<<NGRAPH, 256>>>();
    eqcnt_kernel<<<NGRAPH * NCHUNK, 256>>>();
    eqscan_kernel<<<NGRAPH, 32>>>();
    mark_kernel<<<NGRAPH * NCHUNK, 256>>>();
    readout1_kernel<<<NGRAPH * 3 * RSLICE, 256>>>();
    readout2_kernel<<<NGRAPH * 3, 256>>>();
    mlp_kernel<<<NGRAPH, 256>>>(lw1, lb1, lw2, lb2, lw3, lb3, out);
}

// round 8
// speedup vs baseline: 2.4655x; 1.2805x over previous
#include <cuda_runtime.h>
#include <cuda_bf16.h>
#include <stdint.h>
#include <math.h>

// ---------------- problem constants ----------------
#define NNODES 50000
#define NEDGES 800000
#define NGRAPH 8
#define NPG    6250
#define CIN    512
#define HID    256
#define H3     768
#define KTOP   5000
#define CAP    96
#define NCHUNK 25
#define RSLICE 25

// ---------------- device scratch ----------------
__device__ __align__(256) float g_xw [NNODES * HID];
__device__ __align__(256) float g_x1 [NNODES * HID];
__device__ __align__(256) float g_x2 [NNODES * HID];
__device__ __align__(256) float g_x3 [NNODES * HID];
__device__ __align__(256) float g_deg[NNODES];
__device__ __align__(256) int   g_cnt[NNODES];
__device__ __align__(256) int   g_eperm[NNODES * CAP];
__device__ __align__(256) int   g_src [NEDGES];
__device__ __align__(256) float g_norm[NEDGES];
__device__ __align__(256) float g_sp  [3 * NNODES];
__device__ __align__(256) float g_score[NNODES];
__device__ __align__(256) float g_sel  [NNODES];
__device__ unsigned g_thr[NGRAPH];
__device__ int      g_needeq[NGRAPH];
__device__ int g_eqcnt[NGRAPH * NCHUNK];
__device__ int g_eqoff[NGRAPH * NCHUNK];
__device__ __align__(256) float g_rsum[NGRAPH * 3 * RSLICE * HID];
__device__ __align__(256) float g_rmax[NGRAPH * 3 * RSLICE * HID];
__device__ __align__(256) float g_readout[NGRAPH * 2 * H3];
__device__ float g_pwinv;
__device__ __align__(256) __nv_bfloat16 g_w1h[CIN * HID];
__device__ __align__(256) __nv_bfloat16 g_w1l[CIN * HID];
__device__ __align__(256) __nv_bfloat16 g_w2h[HID * HID];
__device__ __align__(256) __nv_bfloat16 g_w2l[HID * HID];

__device__ __forceinline__ float* buf_select(int sel) {
    switch (sel) {
        case 0:  return g_xw;
        case 1:  return g_x1;
        case 2:  return g_x2;
        default: return g_x3;
    }
}

// ---------------- setup ----------------
__global__ void zero_kernel() {
    int i = blockIdx.x * 256 + threadIdx.x;
    if (i < NNODES) { g_deg[i] = 0.f; g_cnt[i] = 0; }
}

__global__ void fill_kernel(const int* __restrict__ ei,
                            const float* __restrict__ ea) {
    int e = blockIdx.x * 256 + threadIdx.x;
    if (e >= NEDGES) return;
    int s = ei[e];
    int d = ei[NEDGES + e];
    if ((unsigned)s >= NNODES || (unsigned)d >= NNODES) { g_src[e] = 0; return; }
    g_src[e] = s;
    atomicAdd(&g_deg[d], ea[e]);
    int slot = atomicAdd(&g_cnt[d], 1);
    if (slot < CAP) g_eperm[d * CAP + slot] = e;
}

__global__ void dinv_kernel() {
    int i = blockIdx.x * 256 + threadIdx.x;
    if (i < NNODES) g_deg[i] = rsqrtf(g_deg[i] + 1.0f);
}

__global__ void norm_kernel(const int* __restrict__ ei,
                            const float* __restrict__ ea) {
    int e = blockIdx.x * 256 + threadIdx.x;
    if (e >= NEDGES) return;
    int d = ei[NEDGES + e];
    if ((unsigned)d >= NNODES) { g_norm[e] = 0.f; return; }
    g_norm[e] = g_deg[g_src[e]] * ea[e] * g_deg[d];
}

__global__ void splitw_kernel(const float* __restrict__ W, int n, int which) {
    int i = blockIdx.x * 256 + threadIdx.x;
    if (i >= n) return;
    __nv_bfloat16* hi = (which == 0) ? g_w1h : g_w2h;
    __nv_bfloat16* lo = (which == 0) ? g_w1l : g_w2l;
    float w = W[i];
    __nv_bfloat16 h = __float2bfloat16(w);
    float r = w - __bfloat162float(h);
    hi[i] = h;
    lo[i] = __float2bfloat16(r);
}

// ---------------- bf16x3 tensor-core GEMM (ldmatrix version) ----------------
// Tile 128x128x32, 8 warps (4x2), warp tile 32x64, mma m16n8k16.
#define GBM 128
#define GBN 128
#define GBK 32
#define AKP 40     // A smem row stride (bf16): 80B, conflict-free LDSM
#define BNP 136    // B smem row stride (bf16): 272B, conflict-free LDSM

__device__ __forceinline__ uint32_t s2u(const void* p) {
    uint32_t a;
    asm("{ .reg .u64 t; cvta.to.shared.u64 t, %1; cvt.u32.u64 %0, t; }"
        : "=r"(a) : "l"(p));
    return a;
}

__device__ __forceinline__ void ldsm_x4(unsigned* r, uint32_t addr) {
    asm volatile("ldmatrix.sync.aligned.m8n8.x4.shared.b16 {%0,%1,%2,%3}, [%4];"
                 : "=r"(r[0]), "=r"(r[1]), "=r"(r[2]), "=r"(r[3]) : "r"(addr));
}
__device__ __forceinline__ void ldsm_x4_t(unsigned* r, uint32_t addr) {
    asm volatile("ldmatrix.sync.aligned.m8n8.x4.trans.shared.b16 {%0,%1,%2,%3}, [%4];"
                 : "=r"(r[0]), "=r"(r[1]), "=r"(r[2]), "=r"(r[3]) : "r"(addr));
}
__device__ __forceinline__ void mma_bf16(float* d, const unsigned* a, const unsigned* b) {
    asm volatile(
        "mma.sync.aligned.m16n8k16.row.col.f32.bf16.bf16.f32 "
        "{%0,%1,%2,%3}, {%4,%5,%6,%7}, {%8,%9}, {%0,%1,%2,%3};\n"
        : "+f"(d[0]), "+f"(d[1]), "+f"(d[2]), "+f"(d[3])
        : "r"(a[0]), "r"(a[1]), "r"(a[2]), "r"(a[3]), "r"(b[0]), "r"(b[1]));
}

__global__ __launch_bounds__(256) void bgemm_kernel(
    const float* __restrict__ x_ext, int a_sel, int wsel, int K)
{
    const float* A = (a_sel == 0) ? x_ext : (const float*)buf_select(a_sel);
    const __nv_bfloat16* Bh = (wsel == 0) ? g_w1h : g_w2h;
    const __nv_bfloat16* Bl = (wsel == 0) ? g_w1l : g_w2l;
    float* C = g_xw;

    __shared__ __nv_bfloat16 Ash[GBM][AKP];
    __shared__ __nv_bfloat16 Asl[GBM][AKP];
    __shared__ __nv_bfloat16 Bsh[GBK][BNP];   // k-major: row k, 128 n cols
    __shared__ __nv_bfloat16 Bsl[GBK][BNP];

    const int tid = threadIdx.x;
    const int bm = blockIdx.y * GBM;
    const int bn = blockIdx.x * GBN;

    const int lane = tid & 31;
    const int warp = tid >> 5;
    const int wm = warp >> 1;      // 0..3 -> 32 rows
    const int wn = warp & 1;       // 0..1 -> 64 cols
    const int lrow = lane >> 2;
    const int lq   = lane & 3;

    // loaders
    const int a_row = tid >> 1;
    const int a_c0  = (tid & 1) * 16;
    const bool a_ok = (bm + a_row) < NNODES;
    const float* Aptr = A + (size_t)(bm + a_row) * K + a_c0;
    const int b_k  = tid >> 3;             // 0..31
    const int b_n0 = (tid & 7) * 16;       // 0..112

    // smem base addresses (u32) for ldmatrix
    const uint32_t ash0 = s2u(&Ash[0][0]);
    const uint32_t asl0 = s2u(&Asl[0][0]);
    const uint32_t bsh0 = s2u(&Bsh[0][0]);
    const uint32_t bsl0 = s2u(&Bsl[0][0]);
    const int la = lane & 15, ha = lane >> 4;

    float d[2][8][4];
#pragma unroll
    for (int i = 0; i < 2; i++)
#pragma unroll
        for (int j = 0; j < 8; j++)
#pragma unroll
            for (int r = 0; r < 4; r++) d[i][j][r] = 0.f;

    for (int k0 = 0; k0 < K; k0 += GBK) {
        // ---- global prefetch into registers ----
        float4 av[4];
#pragma unroll
        for (int v = 0; v < 4; v++)
            av[v] = a_ok ? *(const float4*)(Aptr + k0 + v * 4)
                         : make_float4(0.f, 0.f, 0.f, 0.f);
        uint4 pbh0 = *(const uint4*)(Bh + (size_t)(k0 + b_k) * HID + bn + b_n0);
        uint4 pbh1 = *(const uint4*)(Bh + (size_t)(k0 + b_k) * HID + bn + b_n0 + 8);
        uint4 pbl0 = *(const uint4*)(Bl + (size_t)(k0 + b_k) * HID + bn + b_n0);
        uint4 pbl1 = *(const uint4*)(Bl + (size_t)(k0 + b_k) * HID + bn + b_n0 + 8);

        if (k0) __syncthreads();   // previous compute done before smem overwrite

        // ---- store A split (packed uint4) ----
        {
            __nv_bfloat16 hbuf[16], lbuf[16];
            float vv[16] = {av[0].x, av[0].y, av[0].z, av[0].w,
                            av[1].x, av[1].y, av[1].z, av[1].w,
                            av[2].x, av[2].y, av[2].z, av[2].w,
                            av[3].x, av[3].y, av[3].z, av[3].w};
#pragma unroll
            for (int j = 0; j < 16; j++) {
                float f = vv[j];
                __nv_bfloat16 h = __float2bfloat16(f);
                hbuf[j] = h;
                lbuf[j] = __float2bfloat16(f - __bfloat162float(h));
            }
            *(uint4*)&Ash[a_row][a_c0]     = *(uint4*)&hbuf[0];
            *(uint4*)&Ash[a_row][a_c0 + 8] = *(uint4*)&hbuf[8];
            *(uint4*)&Asl[a_row][a_c0]     = *(uint4*)&lbuf[0];
            *(uint4*)&Asl[a_row][a_c0 + 8] = *(uint4*)&lbuf[8];
        }
        // ---- store B (straight copy, k-major) ----
        *(uint4*)&Bsh[b_k][b_n0]     = pbh0;
        *(uint4*)&Bsh[b_k][b_n0 + 8] = pbh1;
        *(uint4*)&Bsl[b_k][b_n0]     = pbl0;
        *(uint4*)&Bsl[b_k][b_n0 + 8] = pbl1;
        __syncthreads();

        // ---- compute ----
#pragma unroll
        for (int ks = 0; ks < GBK; ks += 16) {
            unsigned ah[2][4], al[2][4];
#pragma unroll
            for (int fm = 0; fm < 2; fm++) {
                int m = wm * 32 + fm * 16 + la;
                int kc = ks + ha * 8;
                uint32_t off = (uint32_t)(m * AKP + kc) * 2;
                ldsm_x4(ah[fm], ash0 + off);
                ldsm_x4(al[fm], asl0 + off);
            }
#pragma unroll
            for (int fp = 0; fp < 4; fp++) {   // pairs of n8 tiles (16 cols)
                unsigned bh[4], bl[4];
                int kr = ks + la;
                int nc = wn * 64 + fp * 16 + ha * 8;
                uint32_t off = (uint32_t)(kr * BNP + nc) * 2;
                ldsm_x4_t(bh, bsh0 + off);
                ldsm_x4_t(bl, bsl0 + off);
#pragma unroll
                for (int fm = 0; fm < 2; fm++) {
#pragma unroll
                    for (int t = 0; t < 2; t++) {
                        float* acc = d[fm][fp * 2 + t];
                        mma_bf16(acc, ah[fm], &bh[t * 2]);
                        mma_bf16(acc, ah[fm], &bl[t * 2]);
                        mma_bf16(acc, al[fm], &bh[t * 2]);
                    }
                }
            }
        }
    }

    // ---- epilogue ----
#pragma unroll
    for (int fm = 0; fm < 2; fm++) {
#pragma unroll
        for (int fn = 0; fn < 8; fn++) {
            int row = bm + wm * 32 + fm * 16 + lrow;
            int col = bn + wn * 64 + fn * 8 + 2 * lq;
            if (row < NNODES)
                *(float2*)&C[(size_t)row * HID + col] =
                    make_float2(d[fm][fn][0], d[fm][fn][1]);
            if (row + 8 < NNODES)
                *(float2*)&C[(size_t)(row + 8) * HID + col] =
                    make_float2(d[fm][fn][2], d[fm][fn][3]);
        }
    }
}

// ---------------- GCN aggregation + fused score partial ----------------
__global__ __launch_bounds__(256) void agg_kernel(
    const float* __restrict__ bias, int out_sel,
    const float* __restrict__ pwseg, int layer)
{
    const float* xw = g_xw;
    float* out = buf_select(out_sel);
    const int node = blockIdx.x;
    const int t = threadIdx.x;
    __shared__ int   s_src[CAP];
    __shared__ float s_nrm[CAP];
    __shared__ int   s_cnt;
    __shared__ float s_wsum[8];
    if (t == 0) { int c = g_cnt[node]; s_cnt = c < CAP ? c : CAP; }
    __syncthreads();
    const int cnt = s_cnt;
    if (t < cnt) {
        int e = g_eperm[node * CAP + t];
        s_src[t] = g_src[e];
        s_nrm[t] = g_norm[e];
    }
    __syncthreads();

    float d = g_deg[node];
    float acc = d * d * xw[(size_t)node * HID + t] + bias[t];
    int j = 0;
    for (; j + 4 <= cnt; j += 4) {
        float v0 = xw[(size_t)s_src[j + 0] * HID + t];
        float v1 = xw[(size_t)s_src[j + 1] * HID + t];
        float v2 = xw[(size_t)s_src[j + 2] * HID + t];
        float v3 = xw[(size_t)s_src[j + 3] * HID + t];
        acc += s_nrm[j + 0] * v0;
        acc += s_nrm[j + 1] * v1;
        acc += s_nrm[j + 2] * v2;
        acc += s_nrm[j + 3] * v3;
    }
    for (; j < cnt; j++)
        acc += s_nrm[j] * xw[(size_t)s_src[j] * HID + t];

    float v = fmaxf(acc, 0.f);
    out[(size_t)node * HID + t] = v;

    float p = v * pwseg[t];
#pragma unroll
    for (int o = 16; o > 0; o >>= 1) p += __shfl_xor_sync(0xffffffffu, p, o);
    if ((t & 31) == 0) s_wsum[t >> 5] = p;
    __syncthreads();
    if (t == 0) {
        float s = 0.f;
#pragma unroll
        for (int w = 0; w < 8; w++) s += s_wsum[w];
        g_sp[layer * NNODES + node] = s;
    }
}

// ---------------- scoring ----------------
__global__ void pwnorm_kernel(const float* __restrict__ pw) {
    __shared__ float red[256];
    float s = 0.f;
    for (int i = threadIdx.x; i < H3; i += 256) s += pw[i] * pw[i];
    red[threadIdx.x] = s;
    __syncthreads();
    for (int o = 128; o > 0; o >>= 1) {
        if (threadIdx.x < o) red[threadIdx.x] += red[threadIdx.x + o];
        __syncthreads();
    }
    if (threadIdx.x == 0) g_pwinv = rsqrtf(red[0]);
}

__global__ void scorefin_kernel() {
    int i = blockIdx.x * 256 + threadIdx.x;
    if (i >= NNODES) return;
    float dot = g_sp[i] + g_sp[NNODES + i] + g_sp[2 * NNODES + i];
    g_score[i] = 1.f / (1.f + expf(-dot * g_pwinv));
}

// ---------------- exact top-K threshold per graph ----------------
__global__ void radix_kernel() {
    const int g = blockIdx.x;
    const float* sc = g_score + g * NPG;
    __shared__ int hist[256];
    __shared__ unsigned s_prefix;
    __shared__ int s_remaining;
    if (threadIdx.x == 0) { s_prefix = 0u; s_remaining = KTOP; }
    __syncthreads();
    for (int pass = 3; pass >= 0; --pass) {
        hist[threadIdx.x] = 0;
        __syncthreads();
        unsigned prefix = s_prefix;
        int shift = pass * 8;
        for (int i = threadIdx.x; i < NPG; i += 256) {
            unsigned bits = __float_as_uint(sc[i]);
            bool match = (pass == 3) || ((bits >> (shift + 8)) == prefix);
            if (match) atomicAdd(&hist[(bits >> shift) & 255u], 1);
        }
        __syncthreads();
        if (threadIdx.x == 0) {
            int rem = s_remaining;
            unsigned p = s_prefix;
            for (int b = 255; b >= 0; --b) {
                if (hist[b] >= rem) { s_prefix = (p << 8) | (unsigned)b; break; }
                rem -= hist[b];
            }
            s_remaining = rem;
        }
        __syncthreads();
    }
    if (threadIdx.x == 0) { g_thr[g] = s_prefix; g_needeq[g] = s_remaining; }
}

// ---- stable tie resolution, parallel ----
__global__ void eqcnt_kernel() {
    const int ch = blockIdx.x % NCHUNK;
    const int g  = blockIdx.x / NCHUNK;
    const unsigned thr = g_thr[g];
    int i = ch * 256 + threadIdx.x;
    bool eq = (i < NPG) && (__float_as_uint(g_score[g * NPG + i]) == thr);
    unsigned bal = __ballot_sync(0xffffffffu, eq);
    __shared__ int wcnt[8];
    if ((threadIdx.x & 31) == 0) wcnt[threadIdx.x >> 5] = __popc(bal);
    __syncthreads();
    if (threadIdx.x == 0) {
        int s = 0;
#pragma unroll
        for (int w = 0; w < 8; w++) s += wcnt[w];
        g_eqcnt[g * NCHUNK + ch] = s;
    }
}

__global__ void eqscan_kernel() {
    const int g = blockIdx.x;
    if (threadIdx.x == 0) {
        int run = 0;
        for (int c = 0; c < NCHUNK; c++) {
            g_eqoff[g * NCHUNK + c] = run;
            run += g_eqcnt[g * NCHUNK + c];
        }
    }
}

__global__ void mark_kernel() {
    const int ch = blockIdx.x % NCHUNK;
    const int g  = blockIdx.x / NCHUNK;
    const unsigned thr = g_thr[g];
    const int need = g_needeq[g];
    int i = ch * 256 + threadIdx.x;
    float s = 0.f; unsigned bits = 0u;
    if (i < NPG) { s = g_score[g * NPG + i]; bits = __float_as_uint(s); }
    bool eq = (i < NPG) && (bits == thr);
    unsigned bal = __ballot_sync(0xffffffffu, eq);
    int lane = threadIdx.x & 31, warp = threadIdx.x >> 5;
    int lr = __popc(bal & ((1u << lane) - 1u));
    __shared__ int wcnt[8], woff[8];
    if (lane == 0) wcnt[warp] = __popc(bal);
    __syncthreads();
    if (threadIdx.x == 0) {
        int run = 0;
#pragma unroll
        for (int w = 0; w < 8; w++) { woff[w] = run; run += wcnt[w]; }
    }
    __syncthreads();
    if (i < NPG) {
        float out = 0.f;
        if (bits > thr) out = s;
        else if (eq) {
            int rank = g_eqoff[g * NCHUNK + ch] + woff[warp] + lr;
            if (rank < need) out = s;
        }
        g_sel[g * NPG + i] = out;
    }
}

// ---------------- readout, 2-stage ----------------
__global__ __launch_bounds__(256) void readout1_kernel() {
    const int sl = blockIdx.x % RSLICE;
    const int c  = (blockIdx.x / RSLICE) % 3;
    const int g  = blockIdx.x / (RSLICE * 3);
    const float* X = (c == 0) ? g_x1 : ((c == 1) ? g_x2 : g_x3);
    const int f = threadIdx.x;
    const float* sel = g_sel + g * NPG;
    const size_t rowbase = (size_t)g * NPG * HID;
    const int n0 = sl * (NPG / RSLICE), n1 = n0 + NPG / RSLICE;
    float sum0 = 0.f, sum1 = 0.f, mx = 0.f;
    for (int i = n0; i < n1; i += 2) {
        float v0 = sel[i]     * X[rowbase + (size_t)i * HID + f];
        float v1 = sel[i + 1] * X[rowbase + (size_t)(i + 1) * HID + f];
        sum0 += v0; sum1 += v1;
        mx = fmaxf(mx, fmaxf(v0, v1));
    }
    g_rsum[(size_t)blockIdx.x * HID + f] = sum0 + sum1;
    g_rmax[(size_t)blockIdx.x * HID + f] = mx;
}

__global__ __launch_bounds__(256) void readout2_kernel() {
    const int c = blockIdx.x % 3, g = blockIdx.x / 3;
    const int f = threadIdx.x;
    const int base = (g * 3 + c) * RSLICE;
    float sum = 0.f, mx = 0.f;
    for (int k = 0; k < RSLICE; k++) {
        sum += g_rsum[(size_t)(base + k) * HID + f];
        mx = fmaxf(mx, g_rmax[(size_t)(base + k) * HID + f]);
    }
    g_readout[g * 2 * H3 + c * HID + f]      = sum * (1.f / (float)KTOP);
    g_readout[g * 2 * H3 + H3 + c * HID + f] = mx;
}

// ---------------- final MLP ----------------
__global__ __launch_bounds__(256) void mlp_kernel(
    const float* __restrict__ lw1, const float* __restrict__ lb1,
    const float* __restrict__ lw2, const float* __restrict__ lb2,
    const float* __restrict__ lw3, const float* __restrict__ lb3,
    float* __restrict__ out)
{
    const int g = blockIdx.x, t = threadIdx.x;
    __shared__ float r[2 * H3];
    __shared__ float h1[HID];
    __shared__ float h2[HID / 2];
    for (int i = t; i < 2 * H3; i += 256) r[i] = g_readout[g * 2 * H3 + i];
    __syncthreads();
    {
        float a0 = 0.f, a1 = 0.f, a2 = 0.f, a3 = 0.f;
        for (int k = 0; k < 2 * H3; k += 4) {
            a0 += r[k + 0] * lw1[(size_t)(k + 0) * HID + t];
            a1 += r[k + 1] * lw1[(size_t)(k + 1) * HID + t];
            a2 += r[k + 2] * lw1[(size_t)(k + 2) * HID + t];
            a3 += r[k + 3] * lw1[(size_t)(k + 3) * HID + t];
        }
        h1[t] = fmaxf((a0 + a1) + (a2 + a3) + lb1[t], 0.f);
    }
    __syncthreads();
    if (t < 128) {
        float a0 = 0.f, a1 = 0.f;
        for (int k = 0; k < HID; k += 2) {
            a0 += h1[k + 0] * lw2[(size_t)(k + 0) * 128 + t];
            a1 += h1[k + 1] * lw2[(size_t)(k + 1) * 128 + t];
        }
        h2[t] = fmaxf(a0 + a1 + lb2[t], 0.f);
    }
    __syncthreads();
    if (t < 3) {
        float a = lb3[t];
        for (int k = 0; k < 128; k++) a += h2[k] * lw3[k * 3 + t];
        out[g * 3 + t] = a;
    }
}

// ---------------- launch ----------------
extern "C" void kernel_launch(void* const* d_in, const int* in_sizes, int n_in,
                              void* d_out, int out_size)
{
    int ix = -1, iei = -1, iea = -1, iW1 = -1, iW2 = -1, ipw = -1;
    int ilw1 = -1, ilw2 = -1, ilb2 = -1, ilw3 = -1, ilb3 = -1;
    int b256[3] = {-1, -1, -1};
    int nb = 0;
    for (int i = 0; i < n_in; i++) {
        switch (in_sizes[i]) {
            case 25600000: ix   = i; break;
            case 1600000:  iei  = i; break;
            case 800000:   iea  = i; break;
            case 131072:   iW1  = i; break;
            case 65536:    iW2  = i; break;
            case 768:      ipw  = i; break;
            case 393216:   ilw1 = i; break;
            case 32768:    ilw2 = i; break;
            case 128:      ilb2 = i; break;
            case 384:      ilw3 = i; break;
            case 3:        ilb3 = i; break;
            case 256:      if (nb < 3) b256[nb++] = i; break;
            default: break;
        }
    }

    const float* x   = (const float*)d_in[ix];
    const int*   ei  = (const int*)d_in[iei];
    const float* ea  = (const float*)d_in[iea];
    const float* W1  = (const float*)d_in[iW1];
    const float* b1  = (const float*)d_in[b256[0]];
    const float* W2  = (const float*)d_in[iW2];
    const float* b2  = (const float*)d_in[b256[1]];
    const float* pw  = (const float*)d_in[ipw];
    const float* lw1 = (const float*)d_in[ilw1];
    const float* lb1 = (const float*)d_in[b256[2]];
    const float* lw2 = (const float*)d_in[ilw2];
    const float* lb2 = (const float*)d_in[ilb2];
    const float* lw3 = (const float*)d_in[ilw3];
    const float* lb3 = (const float*)d_in[ilb3];
    float* out = (float*)d_out;

    const int nb_nodes = (NNODES + 255) / 256;
    const int nb_edges = (NEDGES + 255) / 256;
    dim3 gemm_grid(HID / GBN, (NNODES + GBM - 1) / GBM);

    zero_kernel<<<nb_nodes, 256>>>();
    fill_kernel<<<nb_edges, 256>>>(ei, ea);
    splitw_kernel<<<(CIN * HID + 255) / 256, 256>>>(W1, CIN * HID, 0);
    splitw_kernel<<<(HID * HID + 255) / 256, 256>>>(W2, HID * HID, 1);
    dinv_kernel<<<nb_nodes, 256>>>();
    norm_kernel<<<nb_edges, 256>>>(ei, ea);

    bgemm_kernel<<<gemm_grid, 256>>>(x, 0, 0, CIN);
    agg_kernel<<<NNODES, 256>>>(b1, 1, pw, 0);

    bgemm_kernel<<<gemm_grid, 256>>>(x, 1, 1, HID);
    agg_kernel<<<NNODES, 256>>>(b2, 2, pw + HID, 1);

    bgemm_kernel<<<gemm_grid, 256>>>(x, 2, 1, HID);
    agg_kernel<<<NNODES, 256>>>(b2, 3, pw + 2 * HID, 2);

    pwnorm_kernel<<<1, 256>>>(pw);
    scorefin_kernel<<<nb_nodes, 256>>>();
    radix_kernel<<<NGRAPH, 256>>>();
    eqcnt_kernel<<<NGRAPH * NCHUNK, 256>>>();
    eqscan_kernel<<<NGRAPH, 32>>>();
    mark_kernel<<<NGRAPH * NCHUNK, 256>>>();
    readout1_kernel<<<NGRAPH * 3 * RSLICE, 256>>>();
    readout2_kernel<<<NGRAPH * 3, 256>>>();
    mlp_kernel<<<NGRAPH, 256>>>(lw1, lb1, lw2, lb2, lw3, lb3, out);
}